// round 1
// baseline (speedup 1.0000x reference)
#include <cuda_runtime.h>
#include <cuda_bf16.h>
#include <cstdint>

#define NUM_PINS_MAX   2000000
#define MAX_BLOCKS     4096

// Scratch: packed (x,y) per pin, and per-block partial sums.
__device__ float2 g_pinxy[NUM_PINS_MAX];
__device__ double g_partials[MAX_BLOCKS];

// ---------------------------------------------------------------------------
// Kernel A: pack x/y halves of pin_pos into float2 array (AoS for gathers)
// ---------------------------------------------------------------------------
__global__ void pack_pins_kernel(const float* __restrict__ pin_pos, int n) {
    int i = blockIdx.x * blockDim.x + threadIdx.x;
    if (i < n) {
        float2 p;
        p.x = pin_pos[i];
        p.y = pin_pos[n + i];
        g_pinxy[i] = p;
    }
}

// ---------------------------------------------------------------------------
// Kernel B: main pair loop. Each iter handles 2 pairs via int4 + float2 loads.
// ---------------------------------------------------------------------------
__global__ void __launch_bounds__(256)
pair_attraction_kernel(const int4* __restrict__ pairs4,   // [npair/2] (a0,b0,a1,b1)
                       const float2* __restrict__ w2,     // [npair/2]
                       int n_quads)                       // = npair/2
{
    const float2* __restrict__ pinxy = g_pinxy;

    float acc0 = 0.0f, acc1 = 0.0f;
    int stride = gridDim.x * blockDim.x;

    for (int i = blockIdx.x * blockDim.x + threadIdx.x; i < n_quads; i += stride) {
        int4   p = pairs4[i];
        float2 w = w2[i];

        float2 pa0 = __ldg(&pinxy[p.x]);
        float2 pb0 = __ldg(&pinxy[p.y]);
        float2 pa1 = __ldg(&pinxy[p.z]);
        float2 pb1 = __ldg(&pinxy[p.w]);

        float dx0 = pa0.x - pb0.x;
        float dy0 = pa0.y - pb0.y;
        float dx1 = pa1.x - pb1.x;
        float dy1 = pa1.y - pb1.y;

        acc0 = fmaf(w.x, fmaf(dx0, dx0, dy0 * dy0), acc0);
        acc1 = fmaf(w.y, fmaf(dx1, dx1, dy1 * dy1), acc1);
    }

    float acc = acc0 + acc1;

    // warp reduce (fp32)
    #pragma unroll
    for (int off = 16; off > 0; off >>= 1)
        acc += __shfl_xor_sync(0xFFFFFFFFu, acc, off);

    // block reduce via shared (double for the cross-warp combine)
    __shared__ double warp_sums[8];   // 256 threads = 8 warps
    int lane = threadIdx.x & 31;
    int wid  = threadIdx.x >> 5;
    if (lane == 0) warp_sums[wid] = (double)acc;
    __syncthreads();

    if (wid == 0) {
        double v = (lane < (blockDim.x >> 5)) ? warp_sums[lane] : 0.0;
        #pragma unroll
        for (int off = 4; off > 0; off >>= 1)
            v += __shfl_xor_sync(0xFFFFFFFFu, v, off);
        if (lane == 0) g_partials[blockIdx.x] = v;
    }
}

// ---------------------------------------------------------------------------
// Kernel C: deterministic final reduction of block partials -> float scalar
// ---------------------------------------------------------------------------
__global__ void final_reduce_kernel(float* __restrict__ out, int n_blocks) {
    __shared__ double warp_sums[32];
    double v = 0.0;
    for (int i = threadIdx.x; i < n_blocks; i += blockDim.x)
        v += g_partials[i];

    #pragma unroll
    for (int off = 16; off > 0; off >>= 1)
        v += __shfl_xor_sync(0xFFFFFFFFu, v, off);

    int lane = threadIdx.x & 31;
    int wid  = threadIdx.x >> 5;
    if (lane == 0) warp_sums[wid] = v;
    __syncthreads();

    if (wid == 0) {
        double s = (lane < (blockDim.x >> 5)) ? warp_sums[lane] : 0.0;
        #pragma unroll
        for (int off = 16; off > 0; off >>= 1)
            s += __shfl_xor_sync(0xFFFFFFFFu, s, off);
        if (lane == 0) out[0] = (float)s;
    }
}

// ---------------------------------------------------------------------------
// Launcher
// ---------------------------------------------------------------------------
extern "C" void kernel_launch(void* const* d_in, const int* in_sizes, int n_in,
                              void* d_out, int out_size) {
    const float* pin_pos = (const float*)d_in[0];
    const float* weights = (const float*)d_in[1];
    const int*   pairs   = (const int*)d_in[2];
    // d_in[3] = pin_mask (unused by the reference computation)

    int n_pins  = in_sizes[0] / 2;          // 2,000,000
    int n_pairs = in_sizes[2] / 2;          // 10,000,000
    int n_quads = n_pairs / 2;              // 5,000,000 (n_pairs is even)

    float* out = (float*)d_out;

    // A: pack pins
    {
        int threads = 256;
        int blocks  = (n_pins + threads - 1) / threads;
        pack_pins_kernel<<<blocks, threads>>>(pin_pos, n_pins);
    }

    // B: main loop
    int threads = 256;
    int blocks  = 148 * 8;                  // 1184 blocks, ~16.5 iters/thread
    if (blocks > MAX_BLOCKS) blocks = MAX_BLOCKS;
    pair_attraction_kernel<<<blocks, threads>>>(
        (const int4*)pairs, (const float2*)weights, n_quads);

    // C: final reduce
    final_reduce_kernel<<<1, 1024>>>(out, blocks);
}